// round 15
// baseline (speedup 1.0000x reference)
#include <cuda_runtime.h>
#include <cuda_fp16.h>
#include <stdint.h>
#include <math.h>

#define Nn 512
#define Ee 16384
#define Dd 1280
#define LMd 1024
#define NFd 256
#define Mm 64
#define KTOT 2560            // A K-extent: [hi|lo]; B dedup'd to Dd
#define KC2 64
#define NSPLIT 4
#define KZC 10               // chunks per split (2560/4/64)
#define NT 20                // n tiles (Dd/64)
#define NSLOT (NSPLIT * NT)  // 80

// ---- device scratch ----
__device__ float g_h[Nn * Dd];
__device__ float g_pd[NSLOT * Nn];
__device__ float g_pm0[NSLOT * Nn];
__device__ float g_pm1[NSLOT * Nn];
__device__ float g_hd[Nn], g_hm0[Nn], g_hm1[Nn];
__device__ float g_c[3];
__device__ float g_p[Nn];
__device__ float g_m0[Nn];
__device__ float g_m1[Nn];
__device__ int   g_off[Nn + 1];
__device__ int   g_es[Ee];
__device__ __half g_A[Nn * KTOT];
__device__ __half g_B[Dd * Dd];      // deduplicated hi copy

__device__ __forceinline__ uint32_t smem_u32(const void* p) {
    uint32_t a;
    asm("{ .reg .u64 t; cvta.to.shared.u64 t, %1; cvt.u32.u64 %0, t; }" : "=r"(a) : "l"(p));
    return a;
}
__device__ __forceinline__ uint32_t pack_h2(float a, float b) {
    __half2 t = __floats2half2_rn(a, b);
    return *(uint32_t*)&t;
}
#define LDSM4(d0, d1, d2, d3, addr)                                          \
    asm volatile("ldmatrix.sync.aligned.m8n8.x4.shared.b16 {%0,%1,%2,%3}, [%4];" \
                 : "=r"(d0), "=r"(d1), "=r"(d2), "=r"(d3) : "r"(addr))
#define LDSM2(d0, d1, addr)                                                  \
    asm volatile("ldmatrix.sync.aligned.m8n8.x2.shared.b16 {%0,%1}, [%2];"   \
                 : "=r"(d0), "=r"(d1) : "r"(addr))

// =================== K1: fused build_h + convW + CSR + const-proj ===================
#define BH_BLKS 640
#define CW_BLKS 1600
__global__ void k_prep(const float* __restrict__ lm, const float* __restrict__ nf,
                       const float* __restrict__ W, const int* __restrict__ dst,
                       const float* __restrict__ bg, const float* __restrict__ Wd,
                       const float* __restrict__ Wm) {
    int b = blockIdx.x;
    int tid = threadIdx.x;
    if (b < BH_BLKS) {
        int idx = b * 256 + tid;
        int i = idx / (Dd / 4), j4 = idx - i * (Dd / 4);
        float4 v;
        if (j4 < LMd / 4) v = *(const float4*)(lm + (i + 1) * LMd + 4 * j4);
        else              v = *(const float4*)(nf + i * NFd + 4 * (j4 - LMd / 4));
        *(float4*)(g_h + i * Dd + 4 * j4) = v;
        return;
    }
    if (b < BH_BLKS + CW_BLKS) {
        int bi = b - BH_BLKS;
        int n0 = (bi % 40) * 32, k0 = (bi / 40) * 32;
        __shared__ float tile[32][33];
        int tx = tid & 31, ty = tid >> 5;
#pragma unroll
        for (int i = 0; i < 4; i++)
            tile[ty + 8 * i][tx] = W[(k0 + ty + 8 * i) * Dd + n0 + tx];
        __syncthreads();
        int p = tid & 15;
        int nr = tid >> 4;
#pragma unroll
        for (int i = 0; i < 2; i++) {
            int nn = nr + 16 * i;
            int n = n0 + nn;
            uint32_t hi2 = pack_h2(tile[2 * p][nn], tile[2 * p + 1][nn]);
            *(uint32_t*)(g_B + (size_t)n * Dd + k0 + 2 * p) = hi2;
        }
        return;
    }
    if (b == BH_BLKS + CW_BLKS) {
        // ---- CSR block ----
        __shared__ int cnt[Nn];
        __shared__ int s2[256];
        __shared__ int pos[Nn];
        int t = tid;
        cnt[t] = 0; cnt[t + 256] = 0;
        __syncthreads();
        for (int e = t; e < Ee; e += 256) atomicAdd(&cnt[dst[e]], 1);
        __syncthreads();
        int c0 = cnt[2 * t], c1 = cnt[2 * t + 1];
        s2[t] = c0 + c1;
        __syncthreads();
        for (int off = 1; off < 256; off <<= 1) {
            int v = (t >= off) ? s2[t - off] : 0;
            __syncthreads();
            s2[t] += v;
            __syncthreads();
        }
        int inc = s2[t];
        g_off[2 * t + 2] = inc;
        g_off[2 * t + 1] = inc - c1;
        if (t == 0) g_off[0] = 0;
        pos[2 * t] = inc - c1 - c0;
        pos[2 * t + 1] = inc - c1;
        __syncthreads();
        for (int e = t; e < Ee; e += 256) {
            int d = dst[e];
            int p = atomicAdd(&pos[d], 1);
            g_es[p] = e;
        }
        return;
    }
    // ---- constant projection block: bg . {Wd, Wm0, Wm1} ----
    {
        float cd = 0.f, c0 = 0.f, c1 = 0.f;
        for (int k = tid; k < Dd; k += 256) {
            float bv = bg[k];
            cd += bv * Wd[k];
            c0 += bv * Wm[2 * k];
            c1 += bv * Wm[2 * k + 1];
        }
        __shared__ float red[3][8];
        int lane = tid & 31, wid = tid >> 5;
#pragma unroll
        for (int o = 16; o; o >>= 1) {
            cd += __shfl_down_sync(0xffffffff, cd, o);
            c0 += __shfl_down_sync(0xffffffff, c0, o);
            c1 += __shfl_down_sync(0xffffffff, c1, o);
        }
        if (lane == 0) { red[0][wid] = cd; red[1][wid] = c0; red[2][wid] = c1; }
        __syncthreads();
        if (tid == 0) {
            float a = 0, bb = 0, c = 0;
#pragma unroll
            for (int q = 0; q < 8; q++) { a += red[0][q]; bb += red[1][q]; c += red[2][q]; }
            g_c[0] = a; g_c[1] = bb; g_c[2] = c;
        }
    }
}

// =================== K2: neigh max + split A + h-projections ===================
__global__ void k_neigh(const int* __restrict__ src, const float* __restrict__ ew,
                        const float* __restrict__ Wd, const float* __restrict__ Wm) {
    int d = blockIdx.x;
    int beg = g_off[d], end = g_off[d + 1];
    int t = threadIdx.x;   // 320
    __shared__ int   ss[128];
    __shared__ float sw[128];
    float4 m = make_float4(-INFINITY, -INFINITY, -INFINITY, -INFINITY);

    for (int c = beg; c < end; c += 128) {
        int nc = min(128, end - c);
        if (t < nc) {
            int e = g_es[c + t];
            ss[t] = src[e];
            sw[t] = ew[e];
        }
        __syncthreads();
        int j = 0;
        for (; j + 4 <= nc; j += 4) {
            const float4* h0 = (const float4*)(g_h + ss[j + 0] * Dd);
            const float4* h1 = (const float4*)(g_h + ss[j + 1] * Dd);
            const float4* h2 = (const float4*)(g_h + ss[j + 2] * Dd);
            const float4* h3 = (const float4*)(g_h + ss[j + 3] * Dd);
            float4 v0 = h0[t], v1 = h1[t], v2 = h2[t], v3 = h3[t];
            float w0 = sw[j + 0], w1 = sw[j + 1], w2 = sw[j + 2], w3 = sw[j + 3];
            m.x = fmaxf(fmaxf(m.x, v0.x * w0), fmaxf(v1.x * w1, fmaxf(v2.x * w2, v3.x * w3)));
            m.y = fmaxf(fmaxf(m.y, v0.y * w0), fmaxf(v1.y * w1, fmaxf(v2.y * w2, v3.y * w3)));
            m.z = fmaxf(fmaxf(m.z, v0.z * w0), fmaxf(v1.z * w1, fmaxf(v2.z * w2, v3.z * w3)));
            m.w = fmaxf(fmaxf(m.w, v0.w * w0), fmaxf(v1.w * w1, fmaxf(v2.w * w2, v3.w * w3)));
        }
        for (; j < nc; j++) {
            const float4* hr = (const float4*)(g_h + ss[j] * Dd);
            float w = sw[j];
            float4 v = hr[t];
            m.x = fmaxf(m.x, v.x * w);
            m.y = fmaxf(m.y, v.y * w);
            m.z = fmaxf(m.z, v.z * w);
            m.w = fmaxf(m.w, v.w * w);
        }
        __syncthreads();
    }
    float4 hv = ((const float4*)(g_h + d * Dd))[t];
    float x0 = hv.x + ((m.x == -INFINITY) ? 0.f : m.x);
    float x1 = hv.y + ((m.y == -INFINITY) ? 0.f : m.y);
    float x2 = hv.z + ((m.z == -INFINITY) ? 0.f : m.z);
    float x3 = hv.w + ((m.w == -INFINITY) ? 0.f : m.w);
    float h0 = __half2float(__float2half_rn(x0));
    float h1 = __half2float(__float2half_rn(x1));
    float h2 = __half2float(__float2half_rn(x2));
    float h3 = __half2float(__float2half_rn(x3));
    uint32_t hiA = pack_h2(x0, x1), hiB = pack_h2(x2, x3);
    uint32_t loA = pack_h2(x0 - h0, x1 - h1), loB = pack_h2(x2 - h2, x3 - h3);
    size_t ab = (size_t)d * KTOT + 4 * t;
    *(uint32_t*)(g_A + ab) = hiA;          *(uint32_t*)(g_A + ab + 2) = hiB;
    *(uint32_t*)(g_A + ab + Dd) = loA;     *(uint32_t*)(g_A + ab + Dd + 2) = loB;

    // ---- h-row projections onto Wd / Wm columns ----
    int c4 = 4 * t;
    float4 wdv = *(const float4*)(Wd + c4);
    float sd = hv.x * wdv.x + hv.y * wdv.y + hv.z * wdv.z + hv.w * wdv.w;
    float4 wm01 = *(const float4*)(Wm + 2 * c4);
    float4 wm23 = *(const float4*)(Wm + 2 * c4 + 4);
    float s0 = hv.x * wm01.x + hv.y * wm01.z + hv.z * wm23.x + hv.w * wm23.z;
    float s1 = hv.x * wm01.y + hv.y * wm01.w + hv.z * wm23.y + hv.w * wm23.w;
    __shared__ float red[3][10];
    int lane = t & 31, wid = t >> 5;
#pragma unroll
    for (int o = 16; o; o >>= 1) {
        sd += __shfl_down_sync(0xffffffff, sd, o);
        s0 += __shfl_down_sync(0xffffffff, s0, o);
        s1 += __shfl_down_sync(0xffffffff, s1, o);
    }
    if (lane == 0) { red[0][wid] = sd; red[1][wid] = s0; red[2][wid] = s1; }
    __syncthreads();
    if (t == 0) {
        float a = 0, bb = 0, c = 0;
#pragma unroll
        for (int q = 0; q < 10; q++) { a += red[0][q]; bb += red[1][q]; c += red[2][q]; }
        g_hd[d] = a; g_hm0[d] = bb; g_hm1[d] = c;
    }
}

// =================== K3: split-K x4 fp16 GEMM, 64x64, projected epilogue ===================
#define ROWB 144
#define ATILE_B (64 * ROWB)        // 9216
#define STAGE_B (2 * ATILE_B)      // 18432
__global__ __launch_bounds__(128, 4) void k_gemm_mma(const float* __restrict__ Wd,
                                                     const float* __restrict__ Wm) {
    extern __shared__ __align__(16) unsigned char smem[];
    int tid = threadIdx.x;
    int lane = tid & 31, warp = tid >> 5;
    int bm = blockIdx.y * 64, bn = blockIdx.x * 64;
    int kz = blockIdx.z;
    int wm = (warp & 1) * 32, wn = (warp >> 1) * 32;
    int kbaseA = kz * (KZC * KC2);
    int kbaseB = kbaseA % Dd;

    uint32_t sbase = smem_u32(smem);
    uint32_t sA[3], sB[3];
#pragma unroll
    for (int st = 0; st < 3; st++) {
        sA[st] = sbase + st * STAGE_B;
        sB[st] = sA[st] + ATILE_B;
    }

    uint32_t aoff = (uint32_t)(wm + ((lane & 8) ? 8 : 0) + (lane & 7)) * ROWB
                  + ((lane & 16) ? 16 : 0);
    int lb = lane & 15;
    uint32_t boff = (uint32_t)(wn + (lb & 7)) * ROWB + ((lb & 8) ? 16 : 0);

    float acc[2][4][4];
#pragma unroll
    for (int mf = 0; mf < 2; mf++)
#pragma unroll
        for (int nf = 0; nf < 4; nf++)
#pragma unroll
            for (int r = 0; r < 4; r++) acc[mf][nf][r] = 0.f;

#define LOAD_CHUNK(cidx, st)                                                        \
    do {                                                                            \
        int kA = kbaseA + (cidx) * KC2;                                             \
        int kB = kbaseB + (cidx) * KC2;                                             \
        _Pragma("unroll")                                                           \
        for (int it = 0; it < 4; it++) {                                            \
            int idx = it * 128 + tid;                                               \
            int row = idx >> 3, seg = idx & 7;                                      \
            uint32_t da = sA[st] + row * ROWB + seg * 16;                           \
            uint32_t db = sB[st] + row * ROWB + seg * 16;                           \
            const void* pa = g_A + (size_t)(bm + row) * KTOT + kA + seg * 8;        \
            const void* pb = g_B + (size_t)(bn + row) * Dd + kB + seg * 8;          \
            asm volatile("cp.async.cg.shared.global [%0], [%1], 16;" :: "r"(da), "l"(pa)); \
            asm volatile("cp.async.cg.shared.global [%0], [%1], 16;" :: "r"(db), "l"(pb)); \
        }                                                                           \
        asm volatile("cp.async.commit_group;" ::: "memory");                        \
    } while (0)

    LOAD_CHUNK(0, 0);
    LOAD_CHUNK(1, 1);

    for (int c = 0; c < KZC; c++) {
        int st = c % 3;
        if (c + 2 < KZC) {
            LOAD_CHUNK(c + 2, (c + 2) % 3);
            asm volatile("cp.async.wait_group 2;" ::: "memory");
        } else if (c + 1 < KZC) {
            asm volatile("cp.async.wait_group 1;" ::: "memory");
        } else {
            asm volatile("cp.async.wait_group 0;" ::: "memory");
        }
        __syncthreads();

        uint32_t aB = sA[st] + aoff;
        uint32_t bB = sB[st] + boff;
#pragma unroll
        for (int ks = 0; ks < 4; ks++) {
            uint32_t a[2][4];
            LDSM4(a[0][0], a[0][1], a[0][2], a[0][3], aB + ks * 32);
            LDSM4(a[1][0], a[1][1], a[1][2], a[1][3], aB + 16 * ROWB + ks * 32);
            uint32_t b[4][2];
#pragma unroll
            for (int nf = 0; nf < 4; nf++)
                LDSM2(b[nf][0], b[nf][1], bB + nf * 8 * ROWB + ks * 32);
#pragma unroll
            for (int mf = 0; mf < 2; mf++)
#pragma unroll
                for (int nf = 0; nf < 4; nf++) {
                    asm volatile(
                        "mma.sync.aligned.m16n8k16.row.col.f32.f16.f16.f32 "
                        "{%0,%1,%2,%3}, {%4,%5,%6,%7}, {%8,%9}, {%0,%1,%2,%3};"
                        : "+f"(acc[mf][nf][0]), "+f"(acc[mf][nf][1]),
                          "+f"(acc[mf][nf][2]), "+f"(acc[mf][nf][3])
                        : "r"(a[mf][0]), "r"(a[mf][1]), "r"(a[mf][2]), "r"(a[mf][3]),
                          "r"(b[nf][0]), "r"(b[nf][1]));
                }
        }
        __syncthreads();
    }

    // ---- epilogue: project acc tile onto Wd / Wm columns ----
    float sd[2][2] = {{0, 0}, {0, 0}};
    float s0[2][2] = {{0, 0}, {0, 0}};
    float s1[2][2] = {{0, 0}, {0, 0}};
#pragma unroll
    for (int nf = 0; nf < 4; nf++) {
        int col = bn + wn + nf * 8 + (lane & 3) * 2;
        float wd0 = Wd[col],         wd1 = Wd[col + 1];
        float w00 = Wm[col * 2],     w01 = Wm[col * 2 + 2];
        float w10 = Wm[col * 2 + 1], w11 = Wm[col * 2 + 3];
#pragma unroll
        for (int mf = 0; mf < 2; mf++) {
            sd[mf][0] += acc[mf][nf][0] * wd0 + acc[mf][nf][1] * wd1;
            sd[mf][1] += acc[mf][nf][2] * wd0 + acc[mf][nf][3] * wd1;
            s0[mf][0] += acc[mf][nf][0] * w00 + acc[mf][nf][1] * w01;
            s0[mf][1] += acc[mf][nf][2] * w00 + acc[mf][nf][3] * w01;
            s1[mf][0] += acc[mf][nf][0] * w10 + acc[mf][nf][1] * w11;
            s1[mf][1] += acc[mf][nf][2] * w10 + acc[mf][nf][3] * w11;
        }
    }
    float* pbd = (float*)smem;            // [64][9]
    float* pb0 = pbd + 64 * 9;
    float* pb1 = pb0 + 64 * 9;
    int slot = (warp >> 1) * 4 + (lane & 3);
#pragma unroll
    for (int mf = 0; mf < 2; mf++) {
        int rl = wm + mf * 16 + (lane >> 2);
        pbd[rl * 9 + slot] = sd[mf][0];  pbd[(rl + 8) * 9 + slot] = sd[mf][1];
        pb0[rl * 9 + slot] = s0[mf][0];  pb0[(rl + 8) * 9 + slot] = s0[mf][1];
        pb1[rl * 9 + slot] = s1[mf][0];  pb1[(rl + 8) * 9 + slot] = s1[mf][1];
    }
    __syncthreads();
    if (tid < 64) {
        float td = 0.f, t0 = 0.f, t1 = 0.f;
#pragma unroll
        for (int q = 0; q < 8; q++) {
            td += pbd[tid * 9 + q];
            t0 += pb0[tid * 9 + q];
            t1 += pb1[tid * 9 + q];
        }
        int sg = kz * NT + blockIdx.x;
        g_pd[sg * Nn + bm + tid]  = td;
        g_pm0[sg * Nn + bm + tid] = t0;
        g_pm1[sg * Nn + bm + tid] = t1;
    }
}

// =================== K4: finalize p / m0 / m1 (slot sum only) ===================
__global__ void k_final(const float* __restrict__ bmv) {
    int row = blockIdx.x * 128 + threadIdx.x;   // grid 4 x 128
    float xd = g_hd[row] + g_c[0];
    float x0 = g_hm0[row] + g_c[1];
    float x1 = g_hm1[row] + g_c[2];
#pragma unroll
    for (int s = 0; s < NSLOT; s++) {
        xd += g_pd[s * Nn + row];
        x0 += g_pm0[s * Nn + row];
        x1 += g_pm1[s * Nn + row];
    }
    g_p[row] = xd;
    g_m0[row] = tanhf(x0 + bmv[0]);
    g_m1[row] = tanhf(x1 + bmv[1]);
}

// =================== K5: dis_pred + mask gather ===================
__global__ void k_dismask(float* __restrict__ out, const float* __restrict__ bd,
                          const int* __restrict__ midx) {
    int t = threadIdx.x;   // 128
    if (blockIdx.x < Nn) {
        int i = blockIdx.x;
        __shared__ float ps[Nn];
        ps[t] = g_p[t]; ps[t + 128] = g_p[t + 128];
        ps[t + 256] = g_p[t + 256]; ps[t + 384] = g_p[t + 384];
        __syncthreads();
        float pi = ps[i];
        float b = bd[0];
        int j = 4 * t;
        float4 o;
        o.x = 1.0f / (1.0f + expf(-(ps[j + 0] - pi + b)));
        o.y = 1.0f / (1.0f + expf(-(ps[j + 1] - pi + b)));
        o.z = 1.0f / (1.0f + expf(-(ps[j + 2] - pi + b)));
        o.w = 1.0f / (1.0f + expf(-(ps[j + 3] - pi + b)));
        *(float4*)(out + i * Nn + j) = o;
    } else if (t < Mm) {
        int r = midx[t];
        out[Nn * Nn + t * 2 + 0] = g_m0[r];
        out[Nn * Nn + t * 2 + 1] = g_m1[r];
    }
}

extern "C" void kernel_launch(void* const* d_in, const int* in_sizes, int n_in,
                              void* d_out, int out_size) {
    const float* lm  = (const float*)d_in[0];
    const float* nf  = (const float*)d_in[1];
    const float* ew  = (const float*)d_in[2];
    const int*   src = (const int*)d_in[3];
    const int*   dst = (const int*)d_in[4];
    const int*   mi  = (const int*)d_in[5];
    const float* Wg  = (const float*)d_in[6];
    const float* bg  = (const float*)d_in[7];
    const float* Wd  = (const float*)d_in[8];
    const float* bd  = (const float*)d_in[9];
    const float* Wm  = (const float*)d_in[10];
    const float* bm  = (const float*)d_in[11];
    float* out = (float*)d_out;

    cudaFuncSetAttribute(k_gemm_mma, cudaFuncAttributeMaxDynamicSharedMemorySize,
                         3 * STAGE_B);

    k_prep<<<BH_BLKS + CW_BLKS + 2, 256>>>(lm, nf, Wg, dst, bg, Wd, Wm);
    k_neigh<<<Nn, 320>>>(src, ew, Wd, Wm);
    k_gemm_mma<<<dim3(NT, Nn / 64, NSPLIT), 128, 3 * STAGE_B>>>(Wd, Wm);
    k_final<<<4, 128>>>(bm);
    k_dismask<<<Nn + 1, 128>>>(out, bd, mi);
}

// round 16
// speedup vs baseline: 1.0900x; 1.0900x over previous
#include <cuda_runtime.h>
#include <cuda_fp16.h>
#include <stdint.h>
#include <math.h>

#define Nn 512
#define Ee 16384
#define Dd 1280
#define LMd 1024
#define NFd 256
#define Mm 64
#define KTOT 2560            // A K-extent: [hi|lo]; B dedup'd to Dd
#define KC2 64
#define NSPLIT 4
#define KZC 10               // chunks per split (2560/4/64)
#define NT 20                // n tiles (Dd/64)
#define NSLOT (NSPLIT * NT)  // 80

// ---- device scratch ----
__device__ float g_h[Nn * Dd];
__device__ float g_pd[NSLOT * Nn];
__device__ float g_pm0[NSLOT * Nn];
__device__ float g_pm1[NSLOT * Nn];
__device__ float g_hd[Nn], g_hm0[Nn], g_hm1[Nn];
__device__ float g_c[3];
__device__ float g_p[Nn];
__device__ float g_m0[Nn];
__device__ float g_m1[Nn];
__device__ int   g_off[Nn + 1];
__device__ int   g_es[Ee];
__device__ __half g_A[Nn * KTOT];
__device__ __half g_B[Dd * Dd];      // deduplicated hi copy

__device__ __forceinline__ uint32_t smem_u32(const void* p) {
    uint32_t a;
    asm("{ .reg .u64 t; cvta.to.shared.u64 t, %1; cvt.u32.u64 %0, t; }" : "=r"(a) : "l"(p));
    return a;
}
__device__ __forceinline__ uint32_t pack_h2(float a, float b) {
    __half2 t = __floats2half2_rn(a, b);
    return *(uint32_t*)&t;
}
#define LDSM4(d0, d1, d2, d3, addr)                                          \
    asm volatile("ldmatrix.sync.aligned.m8n8.x4.shared.b16 {%0,%1,%2,%3}, [%4];" \
                 : "=r"(d0), "=r"(d1), "=r"(d2), "=r"(d3) : "r"(addr))
#define LDSM2(d0, d1, addr)                                                  \
    asm volatile("ldmatrix.sync.aligned.m8n8.x2.shared.b16 {%0,%1}, [%2];"   \
                 : "=r"(d0), "=r"(d1) : "r"(addr))

// =================== K1: fused build_h + convW + CSR + const-proj ===================
#define BH_BLKS 640
#define CW_BLKS 1600
__global__ void k_prep(const float* __restrict__ lm, const float* __restrict__ nf,
                       const float* __restrict__ W, const int* __restrict__ dst,
                       const float* __restrict__ bg, const float* __restrict__ Wd,
                       const float* __restrict__ Wm) {
    int b = blockIdx.x;
    int tid = threadIdx.x;
    if (b < BH_BLKS) {
        int idx = b * 256 + tid;
        int i = idx / (Dd / 4), j4 = idx - i * (Dd / 4);
        float4 v;
        if (j4 < LMd / 4) v = *(const float4*)(lm + (i + 1) * LMd + 4 * j4);
        else              v = *(const float4*)(nf + i * NFd + 4 * (j4 - LMd / 4));
        *(float4*)(g_h + i * Dd + 4 * j4) = v;
        return;
    }
    if (b < BH_BLKS + CW_BLKS) {
        int bi = b - BH_BLKS;
        int n0 = (bi % 40) * 32, k0 = (bi / 40) * 32;
        __shared__ float tile[32][33];
        int tx = tid & 31, ty = tid >> 5;
#pragma unroll
        for (int i = 0; i < 4; i++)
            tile[ty + 8 * i][tx] = W[(k0 + ty + 8 * i) * Dd + n0 + tx];
        __syncthreads();
        int p = tid & 15;
        int nr = tid >> 4;
#pragma unroll
        for (int i = 0; i < 2; i++) {
            int nn = nr + 16 * i;
            int n = n0 + nn;
            uint32_t hi2 = pack_h2(tile[2 * p][nn], tile[2 * p + 1][nn]);
            *(uint32_t*)(g_B + (size_t)n * Dd + k0 + 2 * p) = hi2;
        }
        return;
    }
    if (b == BH_BLKS + CW_BLKS) {
        // ---- CSR block ----
        __shared__ int cnt[Nn];
        __shared__ int s2[256];
        __shared__ int pos[Nn];
        int t = tid;
        cnt[t] = 0; cnt[t + 256] = 0;
        __syncthreads();
        for (int e = t; e < Ee; e += 256) atomicAdd(&cnt[dst[e]], 1);
        __syncthreads();
        int c0 = cnt[2 * t], c1 = cnt[2 * t + 1];
        s2[t] = c0 + c1;
        __syncthreads();
        for (int off = 1; off < 256; off <<= 1) {
            int v = (t >= off) ? s2[t - off] : 0;
            __syncthreads();
            s2[t] += v;
            __syncthreads();
        }
        int inc = s2[t];
        g_off[2 * t + 2] = inc;
        g_off[2 * t + 1] = inc - c1;
        if (t == 0) g_off[0] = 0;
        pos[2 * t] = inc - c1 - c0;
        pos[2 * t + 1] = inc - c1;
        __syncthreads();
        for (int e = t; e < Ee; e += 256) {
            int d = dst[e];
            int p = atomicAdd(&pos[d], 1);
            g_es[p] = e;
        }
        return;
    }
    // ---- constant projection block: bg . {Wd, Wm0, Wm1} ----
    {
        float cd = 0.f, c0 = 0.f, c1 = 0.f;
        for (int k = tid; k < Dd; k += 256) {
            float bv = bg[k];
            cd += bv * Wd[k];
            c0 += bv * Wm[2 * k];
            c1 += bv * Wm[2 * k + 1];
        }
        __shared__ float red[3][8];
        int lane = tid & 31, wid = tid >> 5;
#pragma unroll
        for (int o = 16; o; o >>= 1) {
            cd += __shfl_down_sync(0xffffffff, cd, o);
            c0 += __shfl_down_sync(0xffffffff, c0, o);
            c1 += __shfl_down_sync(0xffffffff, c1, o);
        }
        if (lane == 0) { red[0][wid] = cd; red[1][wid] = c0; red[2][wid] = c1; }
        __syncthreads();
        if (tid == 0) {
            float a = 0, bb = 0, c = 0;
#pragma unroll
            for (int q = 0; q < 8; q++) { a += red[0][q]; bb += red[1][q]; c += red[2][q]; }
            g_c[0] = a; g_c[1] = bb; g_c[2] = c;
        }
    }
}

// =================== K2: neigh max + split A + h-projections ===================
__global__ void k_neigh(const int* __restrict__ src, const float* __restrict__ ew,
                        const float* __restrict__ Wd, const float* __restrict__ Wm) {
    int d = blockIdx.x;
    int beg = g_off[d], end = g_off[d + 1];
    int t = threadIdx.x;   // 320
    __shared__ int   ss[128];
    __shared__ float sw[128];
    float4 m = make_float4(-INFINITY, -INFINITY, -INFINITY, -INFINITY);

    for (int c = beg; c < end; c += 128) {
        int nc = min(128, end - c);
        if (t < nc) {
            int e = g_es[c + t];
            ss[t] = src[e];
            sw[t] = ew[e];
        }
        __syncthreads();
        int j = 0;
        for (; j + 4 <= nc; j += 4) {
            const float4* h0 = (const float4*)(g_h + ss[j + 0] * Dd);
            const float4* h1 = (const float4*)(g_h + ss[j + 1] * Dd);
            const float4* h2 = (const float4*)(g_h + ss[j + 2] * Dd);
            const float4* h3 = (const float4*)(g_h + ss[j + 3] * Dd);
            float4 v0 = h0[t], v1 = h1[t], v2 = h2[t], v3 = h3[t];
            float w0 = sw[j + 0], w1 = sw[j + 1], w2 = sw[j + 2], w3 = sw[j + 3];
            m.x = fmaxf(fmaxf(m.x, v0.x * w0), fmaxf(v1.x * w1, fmaxf(v2.x * w2, v3.x * w3)));
            m.y = fmaxf(fmaxf(m.y, v0.y * w0), fmaxf(v1.y * w1, fmaxf(v2.y * w2, v3.y * w3)));
            m.z = fmaxf(fmaxf(m.z, v0.z * w0), fmaxf(v1.z * w1, fmaxf(v2.z * w2, v3.z * w3)));
            m.w = fmaxf(fmaxf(m.w, v0.w * w0), fmaxf(v1.w * w1, fmaxf(v2.w * w2, v3.w * w3)));
        }
        for (; j < nc; j++) {
            const float4* hr = (const float4*)(g_h + ss[j] * Dd);
            float w = sw[j];
            float4 v = hr[t];
            m.x = fmaxf(m.x, v.x * w);
            m.y = fmaxf(m.y, v.y * w);
            m.z = fmaxf(m.z, v.z * w);
            m.w = fmaxf(m.w, v.w * w);
        }
        __syncthreads();
    }
    float4 hv = ((const float4*)(g_h + d * Dd))[t];
    float x0 = hv.x + ((m.x == -INFINITY) ? 0.f : m.x);
    float x1 = hv.y + ((m.y == -INFINITY) ? 0.f : m.y);
    float x2 = hv.z + ((m.z == -INFINITY) ? 0.f : m.z);
    float x3 = hv.w + ((m.w == -INFINITY) ? 0.f : m.w);
    float h0 = __half2float(__float2half_rn(x0));
    float h1 = __half2float(__float2half_rn(x1));
    float h2 = __half2float(__float2half_rn(x2));
    float h3 = __half2float(__float2half_rn(x3));
    uint32_t hiA = pack_h2(x0, x1), hiB = pack_h2(x2, x3);
    uint32_t loA = pack_h2(x0 - h0, x1 - h1), loB = pack_h2(x2 - h2, x3 - h3);
    size_t ab = (size_t)d * KTOT + 4 * t;
    *(uint32_t*)(g_A + ab) = hiA;          *(uint32_t*)(g_A + ab + 2) = hiB;
    *(uint32_t*)(g_A + ab + Dd) = loA;     *(uint32_t*)(g_A + ab + Dd + 2) = loB;

    // ---- h-row projections onto Wd / Wm columns ----
    int c4 = 4 * t;
    float4 wdv = *(const float4*)(Wd + c4);
    float sd = hv.x * wdv.x + hv.y * wdv.y + hv.z * wdv.z + hv.w * wdv.w;
    float4 wm01 = *(const float4*)(Wm + 2 * c4);
    float4 wm23 = *(const float4*)(Wm + 2 * c4 + 4);
    float s0 = hv.x * wm01.x + hv.y * wm01.z + hv.z * wm23.x + hv.w * wm23.z;
    float s1 = hv.x * wm01.y + hv.y * wm01.w + hv.z * wm23.y + hv.w * wm23.w;
    __shared__ float red[3][10];
    int lane = t & 31, wid = t >> 5;
#pragma unroll
    for (int o = 16; o; o >>= 1) {
        sd += __shfl_down_sync(0xffffffff, sd, o);
        s0 += __shfl_down_sync(0xffffffff, s0, o);
        s1 += __shfl_down_sync(0xffffffff, s1, o);
    }
    if (lane == 0) { red[0][wid] = sd; red[1][wid] = s0; red[2][wid] = s1; }
    __syncthreads();
    if (t == 0) {
        float a = 0, bb = 0, c = 0;
#pragma unroll
        for (int q = 0; q < 10; q++) { a += red[0][q]; bb += red[1][q]; c += red[2][q]; }
        g_hd[d] = a; g_hm0[d] = bb; g_hm1[d] = c;
    }
}

// =================== K3: split-K x4 fp16 GEMM, 64x64, projected epilogue ===================
#define ROWB 144
#define ATILE_B (64 * ROWB)        // 9216
#define STAGE_B (2 * ATILE_B)      // 18432
__global__ __launch_bounds__(128, 4) void k_gemm_mma(const float* __restrict__ Wd,
                                                     const float* __restrict__ Wm) {
    extern __shared__ __align__(16) unsigned char smem[];
    int tid = threadIdx.x;
    int lane = tid & 31, warp = tid >> 5;
    int bm = blockIdx.y * 64, bn = blockIdx.x * 64;
    int kz = blockIdx.z;
    int wm = (warp & 1) * 32, wn = (warp >> 1) * 32;
    int kbaseA = kz * (KZC * KC2);
    int kbaseB = kbaseA % Dd;

    uint32_t sbase = smem_u32(smem);
    uint32_t sA[3], sB[3];
#pragma unroll
    for (int st = 0; st < 3; st++) {
        sA[st] = sbase + st * STAGE_B;
        sB[st] = sA[st] + ATILE_B;
    }

    uint32_t aoff = (uint32_t)(wm + ((lane & 8) ? 8 : 0) + (lane & 7)) * ROWB
                  + ((lane & 16) ? 16 : 0);
    int lb = lane & 15;
    uint32_t boff = (uint32_t)(wn + (lb & 7)) * ROWB + ((lb & 8) ? 16 : 0);

    float acc[2][4][4];
#pragma unroll
    for (int mf = 0; mf < 2; mf++)
#pragma unroll
        for (int nf = 0; nf < 4; nf++)
#pragma unroll
            for (int r = 0; r < 4; r++) acc[mf][nf][r] = 0.f;

#define LOAD_CHUNK(cidx, st)                                                        \
    do {                                                                            \
        int kA = kbaseA + (cidx) * KC2;                                             \
        int kB = kbaseB + (cidx) * KC2;                                             \
        _Pragma("unroll")                                                           \
        for (int it = 0; it < 4; it++) {                                            \
            int idx = it * 128 + tid;                                               \
            int row = idx >> 3, seg = idx & 7;                                      \
            uint32_t da = sA[st] + row * ROWB + seg * 16;                           \
            uint32_t db = sB[st] + row * ROWB + seg * 16;                           \
            const void* pa = g_A + (size_t)(bm + row) * KTOT + kA + seg * 8;        \
            const void* pb = g_B + (size_t)(bn + row) * Dd + kB + seg * 8;          \
            asm volatile("cp.async.cg.shared.global [%0], [%1], 16;" :: "r"(da), "l"(pa)); \
            asm volatile("cp.async.cg.shared.global [%0], [%1], 16;" :: "r"(db), "l"(pb)); \
        }                                                                           \
        asm volatile("cp.async.commit_group;" ::: "memory");                        \
    } while (0)

    LOAD_CHUNK(0, 0);
    LOAD_CHUNK(1, 1);

    for (int c = 0; c < KZC; c++) {
        int st = c % 3;
        if (c + 2 < KZC) {
            LOAD_CHUNK(c + 2, (c + 2) % 3);
            asm volatile("cp.async.wait_group 2;" ::: "memory");
        } else if (c + 1 < KZC) {
            asm volatile("cp.async.wait_group 1;" ::: "memory");
        } else {
            asm volatile("cp.async.wait_group 0;" ::: "memory");
        }
        __syncthreads();

        uint32_t aB = sA[st] + aoff;
        uint32_t bB = sB[st] + boff;
#pragma unroll
        for (int ks = 0; ks < 4; ks++) {
            uint32_t a[2][4];
            LDSM4(a[0][0], a[0][1], a[0][2], a[0][3], aB + ks * 32);
            LDSM4(a[1][0], a[1][1], a[1][2], a[1][3], aB + 16 * ROWB + ks * 32);
            uint32_t b[4][2];
#pragma unroll
            for (int nf = 0; nf < 4; nf++)
                LDSM2(b[nf][0], b[nf][1], bB + nf * 8 * ROWB + ks * 32);
#pragma unroll
            for (int mf = 0; mf < 2; mf++)
#pragma unroll
                for (int nf = 0; nf < 4; nf++) {
                    asm volatile(
                        "mma.sync.aligned.m16n8k16.row.col.f32.f16.f16.f32 "
                        "{%0,%1,%2,%3}, {%4,%5,%6,%7}, {%8,%9}, {%0,%1,%2,%3};"
                        : "+f"(acc[mf][nf][0]), "+f"(acc[mf][nf][1]),
                          "+f"(acc[mf][nf][2]), "+f"(acc[mf][nf][3])
                        : "r"(a[mf][0]), "r"(a[mf][1]), "r"(a[mf][2]), "r"(a[mf][3]),
                          "r"(b[nf][0]), "r"(b[nf][1]));
                }
        }
        __syncthreads();
    }

    // ---- epilogue: project acc tile onto Wd / Wm columns ----
    float sd[2][2] = {{0, 0}, {0, 0}};
    float s0[2][2] = {{0, 0}, {0, 0}};
    float s1[2][2] = {{0, 0}, {0, 0}};
#pragma unroll
    for (int nf = 0; nf < 4; nf++) {
        int col = bn + wn + nf * 8 + (lane & 3) * 2;
        float wd0 = Wd[col],         wd1 = Wd[col + 1];
        float w00 = Wm[col * 2],     w01 = Wm[col * 2 + 2];
        float w10 = Wm[col * 2 + 1], w11 = Wm[col * 2 + 3];
#pragma unroll
        for (int mf = 0; mf < 2; mf++) {
            sd[mf][0] += acc[mf][nf][0] * wd0 + acc[mf][nf][1] * wd1;
            sd[mf][1] += acc[mf][nf][2] * wd0 + acc[mf][nf][3] * wd1;
            s0[mf][0] += acc[mf][nf][0] * w00 + acc[mf][nf][1] * w01;
            s0[mf][1] += acc[mf][nf][2] * w00 + acc[mf][nf][3] * w01;
            s1[mf][0] += acc[mf][nf][0] * w10 + acc[mf][nf][1] * w11;
            s1[mf][1] += acc[mf][nf][2] * w10 + acc[mf][nf][3] * w11;
        }
    }
    float* pbd = (float*)smem;            // [64][9]
    float* pb0 = pbd + 64 * 9;
    float* pb1 = pb0 + 64 * 9;
    int slot = (warp >> 1) * 4 + (lane & 3);
#pragma unroll
    for (int mf = 0; mf < 2; mf++) {
        int rl = wm + mf * 16 + (lane >> 2);
        pbd[rl * 9 + slot] = sd[mf][0];  pbd[(rl + 8) * 9 + slot] = sd[mf][1];
        pb0[rl * 9 + slot] = s0[mf][0];  pb0[(rl + 8) * 9 + slot] = s0[mf][1];
        pb1[rl * 9 + slot] = s1[mf][0];  pb1[(rl + 8) * 9 + slot] = s1[mf][1];
    }
    __syncthreads();
    if (tid < 64) {
        float td = 0.f, t0 = 0.f, t1 = 0.f;
#pragma unroll
        for (int q = 0; q < 8; q++) {
            td += pbd[tid * 9 + q];
            t0 += pb0[tid * 9 + q];
            t1 += pb1[tid * 9 + q];
        }
        int sg = kz * NT + blockIdx.x;
        g_pd[sg * Nn + bm + tid]  = td;
        g_pm0[sg * Nn + bm + tid] = t0;
        g_pm1[sg * Nn + bm + tid] = t1;
    }
}

// =================== K4: finalize p / m0 / m1 (one block per row) ===================
__global__ void k_final(const float* __restrict__ bmv) {
    int row = blockIdx.x;
    int t = threadIdx.x;   // 128
    float xd = 0.f, x0 = 0.f, x1 = 0.f;
    if (t < NSLOT) {
        xd = g_pd[t * Nn + row];
        x0 = g_pm0[t * Nn + row];
        x1 = g_pm1[t * Nn + row];
    }
    __shared__ float red[3][4];
    int lane = t & 31, wid = t >> 5;
#pragma unroll
    for (int o = 16; o; o >>= 1) {
        xd += __shfl_down_sync(0xffffffff, xd, o);
        x0 += __shfl_down_sync(0xffffffff, x0, o);
        x1 += __shfl_down_sync(0xffffffff, x1, o);
    }
    if (lane == 0) { red[0][wid] = xd; red[1][wid] = x0; red[2][wid] = x1; }
    __syncthreads();
    if (t == 0) {
        float Xd = (red[0][0] + red[0][1]) + (red[0][2] + red[0][3]) + g_hd[row] + g_c[0];
        float X0 = (red[1][0] + red[1][1]) + (red[1][2] + red[1][3]) + g_hm0[row] + g_c[1];
        float X1 = (red[2][0] + red[2][1]) + (red[2][2] + red[2][3]) + g_hm1[row] + g_c[2];
        g_p[row] = Xd;
        g_m0[row] = tanhf(X0 + bmv[0]);
        g_m1[row] = tanhf(X1 + bmv[1]);
    }
}

// =================== K5: dis_pred + mask gather ===================
__global__ void k_dismask(float* __restrict__ out, const float* __restrict__ bd,
                          const int* __restrict__ midx) {
    int t = threadIdx.x;   // 128
    if (blockIdx.x < Nn) {
        int i = blockIdx.x;
        __shared__ float ps[Nn];
        ps[t] = g_p[t]; ps[t + 128] = g_p[t + 128];
        ps[t + 256] = g_p[t + 256]; ps[t + 384] = g_p[t + 384];
        __syncthreads();
        float pi = ps[i];
        float b = bd[0];
        int j = 4 * t;
        float4 o;
        o.x = 1.0f / (1.0f + expf(-(ps[j + 0] - pi + b)));
        o.y = 1.0f / (1.0f + expf(-(ps[j + 1] - pi + b)));
        o.z = 1.0f / (1.0f + expf(-(ps[j + 2] - pi + b)));
        o.w = 1.0f / (1.0f + expf(-(ps[j + 3] - pi + b)));
        *(float4*)(out + i * Nn + j) = o;
    } else if (t < Mm) {
        int r = midx[t];
        out[Nn * Nn + t * 2 + 0] = g_m0[r];
        out[Nn * Nn + t * 2 + 1] = g_m1[r];
    }
}

extern "C" void kernel_launch(void* const* d_in, const int* in_sizes, int n_in,
                              void* d_out, int out_size) {
    const float* lm  = (const float*)d_in[0];
    const float* nf  = (const float*)d_in[1];
    const float* ew  = (const float*)d_in[2];
    const int*   src = (const int*)d_in[3];
    const int*   dst = (const int*)d_in[4];
    const int*   mi  = (const int*)d_in[5];
    const float* Wg  = (const float*)d_in[6];
    const float* bg  = (const float*)d_in[7];
    const float* Wd  = (const float*)d_in[8];
    const float* bd  = (const float*)d_in[9];
    const float* Wm  = (const float*)d_in[10];
    const float* bm  = (const float*)d_in[11];
    float* out = (float*)d_out;

    cudaFuncSetAttribute(k_gemm_mma, cudaFuncAttributeMaxDynamicSharedMemorySize,
                         3 * STAGE_B);

    k_prep<<<BH_BLKS + CW_BLKS + 2, 256>>>(lm, nf, Wg, dst, bg, Wd, Wm);
    k_neigh<<<Nn, 320>>>(src, ew, Wd, Wm);
    k_gemm_mma<<<dim3(NT, Nn / 64, NSPLIT), 128, 3 * STAGE_B>>>(Wd, Wm);
    k_final<<<Nn, 128>>>(bm);
    k_dismask<<<Nn + 1, 128>>>(out, bd, mi);
}